// round 16
// baseline (speedup 1.0000x reference)
#include <cuda_runtime.h>
#include <cuda_fp8.h>
#include <cstdint>

#define BB 64
#define SS 576
#define DD 768
#define CC 200
#define NP 208             // padded class dim
#define MT 64              // s-rows per CTA (576 = 9*64, exact)
#define KC 64              // K chunk (2 x k32 steps per barrier)
#define NK 12              // 768/64
#define NSB 3              // B stages

#define WSCALE 32.0f       // attn_w pre-scale into e4m3 normal range
#define WINV   0.03125f

#define B8_STRIDE 80       // bytes per B row (64 data + 16 pad): LDSM conflict-free

#define SZ_BSTG  (NP * B8_STRIDE)                       // 16640 per stage
#define OFF_B8   0
#define OFF_CS   (NSB * SZ_BSTG)                        // 49920
#define SMEM_TOTAL (OFF_CS + NP * 4)                    // 50752

// static scratch (no allocs)
__device__ uint8_t g_w8[NP * DD];                       // e4m3 attn_w * 32
__device__ __align__(16) uint8_t g_a8[(size_t)BB * SS * DD];  // fp8 patch, fragment-permuted per 64B chunk
__device__ float g_rsum[BB * SS];                       // exact f32 rowsums

__device__ __forceinline__ uint32_t smem_u32(const void* p) {
    uint32_t a;
    asm("{ .reg .u64 t; cvta.to.shared.u64 t, %1; cvt.u32.u64 %0, t; }" : "=r"(a) : "l"(p));
    return a;
}
__device__ __forceinline__ void cp_async16(uint32_t dst, const void* src) {
    asm volatile("{ .reg .u64 g; cvta.to.global.u64 g, %1; cp.async.cg.shared.global [%0], [g], 16; }"
                 :: "r"(dst), "l"(src) : "memory");
}
#define CP_COMMIT() asm volatile("cp.async.commit_group;" ::: "memory")
#define CP_WAIT1()  asm volatile("cp.async.wait_group 1;" ::: "memory")

#define LDSM4(r0, r1, r2, r3, addr)                                           \
    asm volatile("ldmatrix.sync.aligned.m8n8.x4.shared.b16 {%0,%1,%2,%3}, [%4];" \
        : "=r"(r0), "=r"(r1), "=r"(r2), "=r"(r3) : "r"(addr))
#define LDSM2(r0, r1, addr)                                                   \
    asm volatile("ldmatrix.sync.aligned.m8n8.x2.shared.b16 {%0,%1}, [%2];"    \
        : "=r"(r0), "=r"(r1) : "r"(addr))

#define MMA8(c, a0, a1, a2, a3, b0, b1)                                       \
    asm volatile("mma.sync.aligned.m16n8k32.row.col.f32.e4m3.e4m3.f32 "       \
        "{%0,%1,%2,%3},{%4,%5,%6,%7},{%8,%9},{%0,%1,%2,%3};"                  \
        : "+f"((c)[0]), "+f"((c)[1]), "+f"((c)[2]), "+f"((c)[3])              \
        : "r"(a0), "r"(a1), "r"(a2), "r"(a3), "r"(b0), "r"(b1))

__device__ __forceinline__ float sigf(float x) { return 1.f / (1.f + __expf(-x)); }

// pack 4 floats -> 4 e4m3 bytes, k ascending low->high byte.
// cvt.e4m3x2 packs: d<7:0>=cvt(second src), d<15:8>=cvt(first src)
__device__ __forceinline__ uint32_t pack4_e4m3(float a, float b, float c, float d) {
    uint16_t lo, hi;
    asm("cvt.rn.satfinite.e4m3x2.f32 %0, %2, %1;" : "=h"(lo) : "f"(a), "f"(b)); // low byte = a
    asm("cvt.rn.satfinite.e4m3x2.f32 %0, %2, %1;" : "=h"(hi) : "f"(c), "f"(d)); // low byte = c
    return (uint32_t)lo | ((uint32_t)hi << 16);
}

// ---------------------------------------------------------------------------
// prep kernel:
//  blocks [0,4608):     patch f32 -> g_a8 (fp8, fragment-permuted) + g_rsum
//  blocks [4608,4686):  attn_w * 32 -> g_w8 (e4m3, zero-padded rows)
//  blocks [4686,6286):  global_scores = class_token @ gc_w^T + gc_b
// ---------------------------------------------------------------------------
__global__ void prep_kernel(const float* __restrict__ patch,
                            const float* __restrict__ aw,
                            const float* __restrict__ ct,
                            const float* __restrict__ gcw,
                            const float* __restrict__ gcb,
                            float* __restrict__ out) {
    int bid  = blockIdx.x;
    int warp = threadIdx.x >> 5;
    int lane = threadIdx.x & 31;
    if (bid < 4608) {
        // one row (b,s) per warp: 768 f32 -> 768 fp8 permuted + rowsum
        int row = bid * 8 + warp;                      // 0..36863
        const float* src = patch + (size_t)row * DD;
        uint8_t* dst = g_a8 + (size_t)row * DD;
        const int c64 = lane >> 4;                     // 0..1
        const int q   = lane & 3;
        const int s16 = (lane & 15) >> 2;
        const int outb = q * 16 + s16 * 4;
        float part = 0.f;
        #pragma unroll
        for (int i = 0; i < 6; ++i) {
            float4 v = *reinterpret_cast<const float4*>(src + lane * 4 + i * 128);
            part += (v.x + v.y) + (v.z + v.w);
            uint32_t u = pack4_e4m3(v.x, v.y, v.z, v.w);
            *reinterpret_cast<uint32_t*>(dst + (c64 + 2 * i) * 64 + outb) = u;
        }
        #pragma unroll
        for (int m = 16; m; m >>= 1) part += __shfl_xor_sync(0xffffffffu, part, m);
        if (lane == 0) g_rsum[row] = part;
    } else if (bid < 4686) {
        int base = (bid - 4608) * 2048 + threadIdx.x * 8;   // 78*2048 = NP*DD
        #pragma unroll
        for (int i = 0; i < 8; i += 4) {
            int idx = base + i;
            int c = idx / DD;
            float s = (c < CC) ? WSCALE : 0.f;
            *reinterpret_cast<uint32_t*>(g_w8 + idx) =
                pack4_e4m3(aw[idx] * s, aw[idx + 1] * s, aw[idx + 2] * s, aw[idx + 3] * s);
        }
    } else {
        int W = (bid - 4686) * 8 + warp;               // 0..12799
        int b = W & 63;
        int c = W >> 6;                                // 0..199
        const float* x = ct + (size_t)b * DD;
        const float* w = gcw + (size_t)c * DD;
        float acc = 0.f;
        #pragma unroll 4
        for (int d = lane; d < DD; d += 32) acc += x[d] * w[d];
        #pragma unroll
        for (int m = 16; m; m >>= 1) acc += __shfl_xor_sync(0xffffffffu, acc, m);
        if (lane == 0) out[b * CC + c] = acc + gcb[c];
    }
}

// ---------------------------------------------------------------------------
// attn kernel: logits = patch @ attn_w^T via fp8 e4m3 mma.sync m16n8k32.
// A: pre-converted, fragment-permuted fp8 -> TWO LDG.128 per warp per KC=64.
//    No smem, no ldmatrix, no cvt, no rowsum in the mainloop.
// B: cp.async fp8 ring (3 stages), ldmatrix; ONE barrier per KC=64.
// ---------------------------------------------------------------------------
__global__ void __launch_bounds__(256, 2)
attn_kernel(const float* __restrict__ attn_b,
            const float* __restrict__ lam,
            float* __restrict__ out) {
    extern __shared__ __align__(16) char smem[];
    float* colsum = (float*)(smem + OFF_CS);
    const uint32_t sb = smem_u32(smem);

    const int tid  = threadIdx.x;
    const int lane = tid & 31;
    const int warp = tid >> 5;
    const int wm   = warp >> 1;          // 0..3
    const int wn   = warp & 1;           // 0..1
    const int g    = lane >> 2;          // 0..7
    const int q    = lane & 3;           // 0..3

    const int b  = blockIdx.y;
    const int s0 = blockIdx.x * MT;

    if (tid < NP) colsum[tid] = 0.f;

    // A fragment bases (permuted layout): rows wm*16+g and +8, lane chunk q*16
    const uint8_t* gA0 = g_a8 + ((size_t)(b * SS + s0 + wm * 16 + g)) * DD + q * 16;
    const uint8_t* gA1 = gA0 + 8 * (size_t)DD;

    // B ldmatrix per-lane byte offset (80B rows: 16B-aligned, conflict-free)
    const uint32_t boff = (uint32_t)(((lane & 7) + ((lane >> 4) & 1) * 8) * B8_STRIDE
                                     + ((lane >> 3) & 1) * 16);

    float acc[13][4];
    #pragma unroll
    for (int j = 0; j < 13; ++j) {
        acc[j][0] = 0.f; acc[j][1] = 0.f; acc[j][2] = 0.f; acc[j][3] = 0.f;
    }

    auto issueB = [&](int kt) {
        uint32_t bdst = sb + OFF_B8 + (kt % NSB) * SZ_BSTG;
        #pragma unroll
        for (int i = 0; i < 4; ++i) {                   // 832 chunks of 16B
            int f = tid + 256 * i;
            if (f < NP * 4) {
                int row = f >> 2, cc = f & 3;
                cp_async16(bdst + row * B8_STRIDE + cc * 16,
                           g_w8 + (size_t)row * DD + kt * KC + cc * 16);
            }
        }
        CP_COMMIT();
    };

    uint4 ua0, ua1;                      // prefetched A fragments (one iter ahead)
    auto loadA = [&](int kt) {
        ua0 = *reinterpret_cast<const uint4*>(gA0 + kt * KC);
        ua1 = *reinterpret_cast<const uint4*>(gA1 + kt * KC);
    };

    issueB(0);
    issueB(1);
    loadA(0);

    for (int kt = 0; kt < NK; ++kt) {
        // extract fragments from prefetched regs, then prefetch next
        const uint32_t a00 = ua0.x, a01 = ua1.x, a02 = ua0.y, a03 = ua1.y;  // k32 step 0
        const uint32_t a10 = ua0.z, a11 = ua1.z, a12 = ua0.w, a13 = ua1.w;  // k32 step 1
        if (kt + 1 < NK) loadA(kt + 1);

        CP_WAIT1();                      // B[kt] arrived (pending <= {B[kt+1]})
        __syncthreads();                 // all warps done with stage (kt-1)%NSB

        if (kt + 2 < NK) issueB(kt + 2); else CP_COMMIT();

        const uint32_t bstage = sb + OFF_B8 + (kt % NSB) * SZ_BSTG
                              + wn * 104 * B8_STRIDE + boff;
        #pragma unroll
        for (int p = 0; p < 6; ++p) {
            uint32_t b0, b1, b2, b3;
            LDSM4(b0, b1, b2, b3, bstage + p * 16 * B8_STRIDE);
            MMA8(acc[2 * p],     a00, a01, a02, a03, b0, b1);
            MMA8(acc[2 * p + 1], a00, a01, a02, a03, b2, b3);
        }
        {
            uint32_t b0, b1;
            LDSM2(b0, b1, bstage + 96 * B8_STRIDE);
            MMA8(acc[12], a00, a01, a02, a03, b0, b1);
        }
        #pragma unroll
        for (int p = 0; p < 6; ++p) {
            uint32_t b0, b1, b2, b3;
            LDSM4(b0, b1, b2, b3, bstage + p * 16 * B8_STRIDE + 32);
            MMA8(acc[2 * p],     a10, a11, a12, a13, b0, b1);
            MMA8(acc[2 * p + 1], a10, a11, a12, a13, b2, b3);
        }
        {
            uint32_t b0, b1;
            LDSM2(b0, b1, bstage + 96 * B8_STRIDE + 32);
            MMA8(acc[12], a10, a11, a12, a13, b0, b1);
        }
    }

    // ---- rowsums from precomputed table ----
    const float rlo = g_rsum[b * SS + s0 + wm * 16 + g];
    const float rhi = g_rsum[b * SS + s0 + wm * 16 + g + 8];

    // ---- epilogue: sigmoid(logit/32 + bias) * rowsum, reduce over s ----
    #pragma unroll
    for (int j = 0; j < 13; ++j) {
        const int ce = wn * 104 + j * 8 + 2 * q;
        float be = (ce     < CC) ? __ldg(&attn_b[ce])     : 0.f;
        float bo = (ce + 1 < CC) ? __ldg(&attn_b[ce + 1]) : 0.f;
        float pe = sigf(acc[j][0] * WINV + be) * rlo + sigf(acc[j][2] * WINV + be) * rhi;
        float po = sigf(acc[j][1] * WINV + bo) * rlo + sigf(acc[j][3] * WINV + bo) * rhi;
        #pragma unroll
        for (int m = 4; m < 32; m <<= 1) {
            pe += __shfl_xor_sync(0xffffffffu, pe, m);
            po += __shfl_xor_sync(0xffffffffu, po, m);
        }
        if (lane < 4) {                  // lane == q
            atomicAdd(&colsum[ce],     pe);
            atomicAdd(&colsum[ce + 1], po);
        }
    }
    __syncthreads();

    if (tid < CC) {
        float scale = __ldg(&lam[0]) * (1.f / (float)(SS * DD));
        atomicAdd(&out[b * CC + tid], scale * colsum[tid]);
    }
}

// ---------------------------------------------------------------------------
// kernel_launch
// inputs: 0 patch (64,576,768) f32 | 1 class_token (64,768) | 2 attn_w (200,768)
//         3 attn_b (200) | 4 gc_w (200,768) | 5 gc_b (200) | 6 lam (1)
// out: (64,200) f32
// ---------------------------------------------------------------------------
extern "C" void kernel_launch(void* const* d_in, const int* in_sizes, int n_in,
                              void* d_out, int out_size) {
    (void)in_sizes; (void)n_in; (void)out_size;
    const float* patch = (const float*)d_in[0];
    const float* ct    = (const float*)d_in[1];
    const float* aw    = (const float*)d_in[2];
    const float* ab    = (const float*)d_in[3];
    const float* gw    = (const float*)d_in[4];
    const float* gb    = (const float*)d_in[5];
    const float* lam   = (const float*)d_in[6];
    float* out = (float*)d_out;

    cudaFuncSetAttribute(attn_kernel, cudaFuncAttributeMaxDynamicSharedMemorySize,
                         SMEM_TOTAL);

    prep_kernel<<<6286, 256>>>(patch, aw, ct, gw, gb, out);
    attn_kernel<<<dim3(SS / MT, BB), 256, SMEM_TOTAL>>>(ab, lam, out);
}